// round 2
// baseline (speedup 1.0000x reference)
#include <cuda_runtime.h>
#include <math.h>

#define B_   32
#define T_   512
#define H_   1024
#define G3   3072
#define NCTA 128

// ---------------- device scratch (static: no cudaMalloc allowed) ----------------
__device__ float        g_GX[(size_t)B_ * T_ * G3];   // [B*T][3H] precomputed gx (201 MB)
__device__ float        g_h[2][B_][H_];               // double-buffered hidden state
__device__ unsigned int g_counters[T_ + 2];           // grid barrier counters (zeroed per replay)

// ---------------- init: zero barrier counters, load initial hidden ----------------
__global__ void init_kernel(const float* __restrict__ hidden) {
    int tid = blockIdx.x * blockDim.x + threadIdx.x;
    if (tid < T_ + 2) g_counters[tid] = 0u;
    for (int i = tid; i < B_ * H_; i += gridDim.x * blockDim.x)
        (&g_h[0][0][0])[i] = hidden[i];
}

// ---------------- GX = emb[x] @ W + b_i   (M=16384, K=1024, N=3072) ----------------
#define BM 128
#define BN 64
#define BK 16

__global__ void __launch_bounds__(256)
gx_kernel(const int* __restrict__ x, const float* __restrict__ emb,
          const float* __restrict__ W, const float* __restrict__ bias) {
    __shared__ float As[BK][BM + 4];   // pad to reduce STS conflicts
    __shared__ float Bs[BK][BN + 4];
    __shared__ int   toks[BM];

    const int m0  = blockIdx.x * BM;
    const int n0  = blockIdx.y * BN;
    const int tid = threadIdx.x;       // 256
    const int ty  = tid >> 4;          // 0..15 (row group)
    const int tx  = tid & 15;          // 0..15 (col group)

    if (tid < BM) toks[tid] = x[m0 + tid];
    __syncthreads();

    float acc[8][4];
#pragma unroll
    for (int i = 0; i < 8; i++)
#pragma unroll
        for (int c = 0; c < 4; c++) acc[i][c] = 0.0f;

    for (int k0 = 0; k0 < H_; k0 += BK) {
        // load A tile (gathered embedding rows), store transposed As[k][m]
#pragma unroll
        for (int r = 0; r < 2; r++) {
            int s   = tid + r * 256;      // 0..511
            int row = s >> 2;             // 0..127
            int kq  = s & 3;              // 0..3 (float4 within 16 k's)
            float4 v = *(const float4*)(emb + (size_t)toks[row] * H_ + k0 + kq * 4);
            As[kq * 4 + 0][row] = v.x;
            As[kq * 4 + 1][row] = v.y;
            As[kq * 4 + 2][row] = v.z;
            As[kq * 4 + 3][row] = v.w;
        }
        // load B tile
        {
            int kk = tid >> 4, c4 = tid & 15;
            float4 v = *(const float4*)(W + (size_t)(k0 + kk) * G3 + n0 + c4 * 4);
            *(float4*)&Bs[kk][c4 * 4] = v;
        }
        __syncthreads();

#pragma unroll
        for (int kk = 0; kk < BK; kk++) {
            float4 a0 = *(const float4*)&As[kk][ty * 8];
            float4 a1 = *(const float4*)&As[kk][ty * 8 + 4];
            float4 b  = *(const float4*)&Bs[kk][tx * 4];
            float a[8] = {a0.x, a0.y, a0.z, a0.w, a1.x, a1.y, a1.z, a1.w};
            float bb[4] = {b.x, b.y, b.z, b.w};
#pragma unroll
            for (int i = 0; i < 8; i++)
#pragma unroll
                for (int c = 0; c < 4; c++) acc[i][c] += a[i] * bb[c];
        }
        __syncthreads();
    }

    // epilogue: add input bias b_i = bias[0][:], store to g_GX
    float4 bi = *(const float4*)(bias + n0 + tx * 4);
#pragma unroll
    for (int i = 0; i < 8; i++) {
        int m = m0 + ty * 8 + i;
        float4 o;
        o.x = acc[i][0] + bi.x;
        o.y = acc[i][1] + bi.y;
        o.z = acc[i][2] + bi.z;
        o.w = acc[i][3] + bi.w;
        *(float4*)(g_GX + (size_t)m * G3 + n0 + tx * 4) = o;
    }
}

// ---------------- persistent recurrence: 128 CTAs x 256 thr, 1 CTA/SM ----------------
// CTA c owns units j in [8c, 8c+8). Lane = (batch_local 0..3, unit 0..7), warp = 4 batches.
// Rs smem layout: Rs[k*32 + u*4 + g], g in {0=z,1=r,2=n}, slot 3 = pad.
__global__ void __launch_bounds__(256, 1)
gru_persist(const int* __restrict__ x, const float* __restrict__ RT,
            const float* __restrict__ bias, float* __restrict__ out, int out_size) {
    extern __shared__ float Rs[];   // 1024*32 floats = 128 KB

    const int c   = blockIdx.x;            // 0..127
    const int j0  = c * 8;
    const int tid = threadIdx.x;
    const int w   = tid >> 5;              // warp 0..7
    const int l   = tid & 31;
    const int bl  = l >> 3;                // 0..3
    const int u   = l & 7;                 // 0..7
    const int b   = w * 4 + bl;            // batch 0..31
    const int j   = j0 + u;                // global unit

    // stage this CTA's 24 RT columns into smem (once for all 512 steps)
    for (int s = tid; s < 1024 * 24; s += 256) {
        int k  = s / 24;
        int r  = s % 24;
        int g  = r >> 3;
        int uu = r & 7;
        Rs[k * 32 + uu * 4 + g] = RT[(size_t)k * G3 + g * 1024 + j0 + uu];
    }
    // recurrent bias b_r = bias[1][:]
    const float brz = bias[G3 + 0 * 1024 + j];
    const float brr = bias[G3 + 1 * 1024 + j];
    const float brn = bias[G3 + 2 * 1024 + j];
    __syncthreads();

    const float* gx_base = g_GX + (size_t)b * T_ * G3;   // row m = b*T + t
    const int*   xb      = x + b * T_;
    float*       out_b   = out + (size_t)b * T_ * H_;
    const bool   write_state = (out_size >= B_ * T_ * H_ + B_ * H_);

    for (int t = 0; t < T_; t++) {
        const float* hrow = &g_h[t & 1][b][0];
        float az = 0.0f, ar = 0.0f, an = 0.0f;

#pragma unroll 8
        for (int k = 0; k < H_; k += 4) {
            float4 h4 = __ldcg((const float4*)(hrow + k));   // L2 (bypass stale L1)
            float4 r0 = *(const float4*)&Rs[(k + 0) * 32 + u * 4];
            float4 r1 = *(const float4*)&Rs[(k + 1) * 32 + u * 4];
            float4 r2 = *(const float4*)&Rs[(k + 2) * 32 + u * 4];
            float4 r3 = *(const float4*)&Rs[(k + 3) * 32 + u * 4];
            az += h4.x * r0.x; ar += h4.x * r0.y; an += h4.x * r0.z;
            az += h4.y * r1.x; ar += h4.y * r1.y; an += h4.y * r1.z;
            az += h4.z * r2.x; ar += h4.z * r2.y; an += h4.z * r2.z;
            az += h4.w * r3.x; ar += h4.w * r3.y; an += h4.w * r3.z;
        }

        // gate math
        const float* gx = gx_base + (size_t)t * G3;
        float xz = gx[j];
        float xr = gx[1024 + j];
        float xn = gx[2048 + j];
        float hp = __ldcg(hrow + j);

        float zz = 1.0f / (1.0f + expf(-(xz + az + brz)));
        float rr = 1.0f / (1.0f + expf(-(xr + ar + brr)));
        float hh = tanhf(xn + rr * (an + brn));
        float hnew = zz * hp + (1.0f - zz) * hh;
        if (xb[t] == 0) hnew = hp;     // mask_zero: carry state through padding

        out_b[(size_t)t * H_ + j] = hnew;
        g_h[(t + 1) & 1][b][j]    = hnew;
        if (t == T_ - 1 && write_state)
            out[(size_t)B_ * T_ * H_ + b * H_ + j] = hnew;

        // grid barrier (skip after last step)
        if (t < T_ - 1) {
            __threadfence();
            __syncthreads();
            if (tid == 0) {
                atomicAdd(&g_counters[t + 1], 1u);
                while (*(volatile unsigned int*)&g_counters[t + 1] < (unsigned)NCTA) { }
            }
            __syncthreads();
        }
    }
}

// ---------------- launch ----------------
extern "C" void kernel_launch(void* const* d_in, const int* in_sizes, int n_in,
                              void* d_out, int out_size) {
    const int*   x      = (const int*)d_in[0];
    const float* hidden = (const float*)d_in[1];
    const float* emb    = (const float*)d_in[2];
    const float* W      = (const float*)d_in[3];
    const float* RT     = (const float*)d_in[4];
    const float* bias   = (const float*)d_in[5];
    float*       out    = (float*)d_out;

    cudaFuncSetAttribute(gru_persist, cudaFuncAttributeMaxDynamicSharedMemorySize, 131072);

    init_kernel<<<64, 256>>>(hidden);

    dim3 grid_gx(16384 / BM, G3 / BN);   // 128 x 48
    gx_kernel<<<grid_gx, 256>>>(x, emb, W, bias);

    gru_persist<<<NCTA, 256, 131072>>>(x, RT, bias, out, out_size);
}

// round 3
// speedup vs baseline: 1.5886x; 1.5886x over previous
#include <cuda_runtime.h>
#include <math.h>

#define B_   32
#define T_   512
#define H_   1024
#define G3   3072
#define NCTA 128

typedef unsigned long long u64;

// ---------------- device scratch (static: no cudaMalloc allowed) ----------------
__device__ float        g_GX[(size_t)B_ * T_ * G3];   // [B*T][3H] precomputed gx
__device__ float        g_h2[2][H_][B_];              // hidden state, TRANSPOSED [k][b], double buffered
__device__ unsigned int g_counters[T_ + 2];

// ---------------- f32x2 helpers (sm_103a packed fp32 FMA) ----------------
__device__ __forceinline__ void fma2(u64 &d, u64 a, u64 b) {
    asm("fma.rn.f32x2 %0, %1, %2, %0;" : "+l"(d) : "l"(a), "l"(b));
}
__device__ __forceinline__ u64 splat2(float v) {
    u64 r; asm("mov.b64 %0, {%1, %1};" : "=l"(r) : "f"(v)); return r;
}
__device__ __forceinline__ float2 unpk(u64 v) {
    float2 r; asm("mov.b64 {%0, %1}, %2;" : "=f"(r.x), "=f"(r.y) : "l"(v)); return r;
}

// ---------------- init: zero counters, transpose initial hidden ----------------
__global__ void init_kernel(const float* __restrict__ hidden) {
    int tid = blockIdx.x * blockDim.x + threadIdx.x;
    if (tid < T_ + 2) g_counters[tid] = 0u;
    for (int i = tid; i < B_ * H_; i += gridDim.x * blockDim.x) {
        int b = i / H_, j = i % H_;
        g_h2[0][j][b] = hidden[i];
    }
}

// ---------------- GX = emb[x] @ W + b_i   (M=16384, K=1024, N=3072), f32x2 ----------------
#define BM 128
#define BN 64
#define BK 16

__global__ void __launch_bounds__(256)
gx_kernel(const int* __restrict__ x, const float* __restrict__ emb,
          const float* __restrict__ W, const float* __restrict__ bias) {
    __shared__ float As[BK][BM + 4];
    __shared__ float Bs[BK][BN + 4];
    __shared__ int   toks[BM];

    const int m0  = blockIdx.x * BM;
    const int n0  = blockIdx.y * BN;
    const int tid = threadIdx.x;
    const int ty  = tid >> 4;          // 0..15
    const int tx  = tid & 15;          // 0..15

    if (tid < BM) toks[tid] = x[m0 + tid];
    __syncthreads();

    u64 acc[4][4];                     // [m-pair][n] packed (m even, m odd)
#pragma unroll
    for (int p = 0; p < 4; p++)
#pragma unroll
        for (int c = 0; c < 4; c++) acc[p][c] = 0ull;

    for (int k0 = 0; k0 < H_; k0 += BK) {
#pragma unroll
        for (int r = 0; r < 2; r++) {
            int s   = tid + r * 256;
            int row = s >> 2;
            int kq  = s & 3;
            float4 v = *(const float4*)(emb + (size_t)toks[row] * H_ + k0 + kq * 4);
            As[kq * 4 + 0][row] = v.x;
            As[kq * 4 + 1][row] = v.y;
            As[kq * 4 + 2][row] = v.z;
            As[kq * 4 + 3][row] = v.w;
        }
        {
            int kk = tid >> 4, c4 = tid & 15;
            float4 v = *(const float4*)(W + (size_t)(k0 + kk) * G3 + n0 + c4 * 4);
            *(float4*)&Bs[kk][c4 * 4] = v;
        }
        __syncthreads();

#pragma unroll
        for (int kk = 0; kk < BK; kk++) {
            ulonglong2 av0 = *(const ulonglong2*)&As[kk][ty * 8];      // pairs 0,1
            ulonglong2 av1 = *(const ulonglong2*)&As[kk][ty * 8 + 4];  // pairs 2,3
            float4 bq = *(const float4*)&Bs[kk][tx * 4];
            u64 b0 = splat2(bq.x), b1 = splat2(bq.y), b2 = splat2(bq.z), b3 = splat2(bq.w);
            fma2(acc[0][0], av0.x, b0); fma2(acc[0][1], av0.x, b1);
            fma2(acc[0][2], av0.x, b2); fma2(acc[0][3], av0.x, b3);
            fma2(acc[1][0], av0.y, b0); fma2(acc[1][1], av0.y, b1);
            fma2(acc[1][2], av0.y, b2); fma2(acc[1][3], av0.y, b3);
            fma2(acc[2][0], av1.x, b0); fma2(acc[2][1], av1.x, b1);
            fma2(acc[2][2], av1.x, b2); fma2(acc[2][3], av1.x, b3);
            fma2(acc[3][0], av1.y, b0); fma2(acc[3][1], av1.y, b1);
            fma2(acc[3][2], av1.y, b2); fma2(acc[3][3], av1.y, b3);
        }
        __syncthreads();
    }

    float4 biv = *(const float4*)(bias + n0 + tx * 4);
#pragma unroll
    for (int p = 0; p < 4; p++) {
        float2 c0 = unpk(acc[p][0]), c1 = unpk(acc[p][1]);
        float2 c2 = unpk(acc[p][2]), c3 = unpk(acc[p][3]);
        int m = m0 + ty * 8 + p * 2;
        float4 oe = {c0.x + biv.x, c1.x + biv.y, c2.x + biv.z, c3.x + biv.w};
        float4 oo = {c0.y + biv.x, c1.y + biv.y, c2.y + biv.z, c3.y + biv.w};
        *(float4*)(g_GX + (size_t)m * G3 + n0 + tx * 4)       = oe;
        *(float4*)(g_GX + (size_t)(m + 1) * G3 + n0 + tx * 4) = oo;
    }
}

// ---------------- persistent recurrence ----------------
// CTA c owns units j in [8c, 8c+8).
// Mapping A (matvec): tid = u(8) x bo(4) x ks(8); thread: unit u, batches 8bo..8bo+7,
//   k-slice [128ks, 128ks+128). R loaded ONCE per (k,u,g) via LDS.32, splat, reused
//   across 8 batches via f32x2 (h packed along batch thanks to h[k][b] layout).
// Mapping B (gates): tid = u2(8) x b2(32); reduces 8 k-slice partials, applies GRU math.
// Smem: Rs[k*24 + g*8 + u] (96KB) + red[(ks*8+u)*100 + g*32 + bo*8 + bl] (25.6KB).
__global__ void __launch_bounds__(256, 1)
gru_persist(const int* __restrict__ x, const float* __restrict__ RT,
            const float* __restrict__ bias, float* __restrict__ out, int out_size) {
    extern __shared__ float sm[];
    float* Rs  = sm;            // 24576 floats
    float* red = sm + 24576;    // 6400 floats

    const int c   = blockIdx.x;
    const int j0  = c * 8;
    const int tid = threadIdx.x;
    // mapping A
    const int u  = tid & 7;
    const int bo = (tid >> 3) & 3;
    const int ks = tid >> 5;            // warp index = k-slice
    // mapping B
    const int u2 = tid & 7;
    const int b2 = tid >> 3;            // 0..31
    const int j2 = j0 + u2;

    // stage R (once for all steps): Rs[k*24 + g*8 + u]
    for (int s = tid; s < 1024 * 24; s += 256) {
        int k = s / 24, r = s % 24, g = r >> 3, uu = r & 7;
        Rs[k * 24 + g * 8 + uu] = RT[(size_t)k * G3 + g * 1024 + j0 + uu];
    }
    const float brz = bias[G3 + j2];
    const float brr = bias[G3 + 1024 + j2];
    const float brn = bias[G3 + 2048 + j2];
    __syncthreads();

    const float* gx_row = g_GX + (size_t)b2 * T_ * G3;
    const int*   xrow   = x + b2 * T_;
    const int    k0     = ks * 128;
    const int    redw   = (ks * 8 + u) * 100;          // writer word base
    u64* redu = (u64*)red;
    const int    rb     = (redw + bo * 8) >> 1;        // u64 index; +16 per gate
    const int    rdbase = b2 & 7;                      // bl
    const int    rdbo   = (b2 >> 3) * 8;
    const bool   write_state = (out_size >= B_ * T_ * H_ + B_ * H_);

    for (int t = 0; t < T_; t++) {
        const float* hcur = &g_h2[t & 1][0][0];

        // prefetch gate-phase inputs (mapping B) before the matvec
        float xz = __ldcs(gx_row + (size_t)t * G3 + j2);
        float xr = __ldcs(gx_row + (size_t)t * G3 + 1024 + j2);
        float xn = __ldcs(gx_row + (size_t)t * G3 + 2048 + j2);
        float hp = __ldcg(hcur + j2 * B_ + b2);
        int   tok = xrow[t];

        // ---- matvec partial over k-slice (mapping A) ----
        u64 az0 = 0, az1 = 0, az2 = 0, az3 = 0;
        u64 ar0 = 0, ar1 = 0, ar2 = 0, ar3 = 0;
        u64 an0 = 0, an1 = 0, an2 = 0, an3 = 0;
        const float* hk = hcur + (size_t)k0 * B_ + bo * 8;
        const float* rk = Rs + k0 * 24 + u;
#pragma unroll 4
        for (int k = 0; k < 128; k++) {
            ulonglong2 ha = __ldcg((const ulonglong2*)hk);        // batches (0,1),(2,3) of octet
            ulonglong2 hb = __ldcg((const ulonglong2*)(hk + 4));  // batches (4,5),(6,7)
            u64 rz = splat2(rk[0]);
            u64 rr = splat2(rk[8]);
            u64 rn = splat2(rk[16]);
            fma2(az0, ha.x, rz); fma2(az1, ha.y, rz); fma2(az2, hb.x, rz); fma2(az3, hb.y, rz);
            fma2(ar0, ha.x, rr); fma2(ar1, ha.y, rr); fma2(ar2, hb.x, rr); fma2(ar3, hb.y, rr);
            fma2(an0, ha.x, rn); fma2(an1, ha.y, rn); fma2(an2, hb.x, rn); fma2(an3, hb.y, rn);
            hk += B_; rk += 24;
        }
        redu[rb + 0]  = az0; redu[rb + 1]  = az1; redu[rb + 2]  = az2; redu[rb + 3]  = az3;
        redu[rb + 16] = ar0; redu[rb + 17] = ar1; redu[rb + 18] = ar2; redu[rb + 19] = ar3;
        redu[rb + 32] = an0; redu[rb + 33] = an1; redu[rb + 34] = an2; redu[rb + 35] = an3;
        __syncthreads();

        // ---- reduce + gates (mapping B) ----
        float az = 0.0f, ar = 0.0f, an = 0.0f;
#pragma unroll
        for (int kss = 0; kss < 8; kss++) {
            int o = (kss * 8 + u2) * 100 + rdbo + rdbase;
            az += red[o];
            ar += red[o + 32];
            an += red[o + 64];
        }
        float zz = 1.0f / (1.0f + expf(-(xz + az + brz)));
        float rg = 1.0f / (1.0f + expf(-(xr + ar + brr)));
        float hh = tanhf(xn + rg * (an + brn));
        float hnew = zz * hp + (1.0f - zz) * hh;
        if (tok == 0) hnew = hp;

        out[((size_t)b2 * T_ + t) * H_ + j2] = hnew;
        g_h2[(t + 1) & 1][j2][b2] = hnew;
        if (t == T_ - 1 && write_state)
            out[(size_t)B_ * T_ * H_ + (size_t)b2 * H_ + j2] = hnew;

        // ---- grid barrier ----
        if (t < T_ - 1) {
            __threadfence();
            __syncthreads();
            if (tid == 0) {
                atomicAdd(&g_counters[t + 1], 1u);
                while (*(volatile unsigned int*)&g_counters[t + 1] < (unsigned)NCTA) { }
                __threadfence();
            }
            __syncthreads();
        }
    }
}

// ---------------- launch ----------------
extern "C" void kernel_launch(void* const* d_in, const int* in_sizes, int n_in,
                              void* d_out, int out_size) {
    const int*   x      = (const int*)d_in[0];
    const float* hidden = (const float*)d_in[1];
    const float* emb    = (const float*)d_in[2];
    const float* W      = (const float*)d_in[3];
    const float* RT     = (const float*)d_in[4];
    const float* bias   = (const float*)d_in[5];
    float*       out    = (float*)d_out;

    const int smem = (24576 + 6400) * 4;   // 123904 B
    cudaFuncSetAttribute(gru_persist, cudaFuncAttributeMaxDynamicSharedMemorySize, smem);

    init_kernel<<<64, 256>>>(hidden);

    dim3 grid_gx(16384 / BM, G3 / BN);
    gx_kernel<<<grid_gx, 256>>>(x, emb, W, bias);

    gru_persist<<<NCTA, 256, smem>>>(x, RT, bias, out, out_size);
}

// round 4
// speedup vs baseline: 2.1813x; 1.3731x over previous
#include <cuda_runtime.h>
#include <math.h>

#define B_   32
#define T_   512
#define H_   1024
#define G3   3072
#define NCTA 128
#define NTHR 512

typedef unsigned long long u64;

// ---------------- device scratch (static: no cudaMalloc allowed) ----------------
__device__ float        g_GX[(size_t)B_ * T_ * G3];   // [B*T][3H] precomputed gx
__device__ float        g_h2[2][H_][B_];              // hidden state, transposed [k][b]
__device__ unsigned int g_counters[T_ + 2];

// ---------------- f32x2 helpers ----------------
__device__ __forceinline__ void fma2(u64 &d, u64 a, u64 b) {
    asm("fma.rn.f32x2 %0, %1, %2, %0;" : "+l"(d) : "l"(a), "l"(b));
}
__device__ __forceinline__ u64 splat2(float v) {
    u64 r; asm("mov.b64 %0, {%1, %1};" : "=l"(r) : "f"(v)); return r;
}
__device__ __forceinline__ float2 unpk(u64 v) {
    float2 r; asm("mov.b64 {%0, %1}, %2;" : "=f"(r.x), "=f"(r.y) : "l"(v)); return r;
}

// ---------------- init ----------------
__global__ void init_kernel(const float* __restrict__ hidden) {
    int tid = blockIdx.x * blockDim.x + threadIdx.x;
    if (tid < T_ + 2) g_counters[tid] = 0u;
    for (int i = tid; i < B_ * H_; i += gridDim.x * blockDim.x) {
        int b = i / H_, j = i % H_;
        g_h2[0][j][b] = hidden[i];
    }
}

// ---------------- GX = emb[x] @ W + b_i   (M=16384, K=1024, N=3072), f32x2 ----------------
#define BM 128
#define BN 64
#define BK 16

__global__ void __launch_bounds__(256)
gx_kernel(const int* __restrict__ x, const float* __restrict__ emb,
          const float* __restrict__ W, const float* __restrict__ bias) {
    __shared__ float As[BK][BM + 4];
    __shared__ float Bs[BK][BN + 4];
    __shared__ int   toks[BM];

    const int m0  = blockIdx.x * BM;
    const int n0  = blockIdx.y * BN;
    const int tid = threadIdx.x;
    const int ty  = tid >> 4;
    const int tx  = tid & 15;

    if (tid < BM) toks[tid] = x[m0 + tid];
    __syncthreads();

    u64 acc[4][4];
#pragma unroll
    for (int p = 0; p < 4; p++)
#pragma unroll
        for (int c = 0; c < 4; c++) acc[p][c] = 0ull;

    for (int k0 = 0; k0 < H_; k0 += BK) {
#pragma unroll
        for (int r = 0; r < 2; r++) {
            int s   = tid + r * 256;
            int row = s >> 2;
            int kq  = s & 3;
            float4 v = *(const float4*)(emb + (size_t)toks[row] * H_ + k0 + kq * 4);
            As[kq * 4 + 0][row] = v.x;
            As[kq * 4 + 1][row] = v.y;
            As[kq * 4 + 2][row] = v.z;
            As[kq * 4 + 3][row] = v.w;
        }
        {
            int kk = tid >> 4, c4 = tid & 15;
            float4 v = *(const float4*)(W + (size_t)(k0 + kk) * G3 + n0 + c4 * 4);
            *(float4*)&Bs[kk][c4 * 4] = v;
        }
        __syncthreads();

#pragma unroll
        for (int kk = 0; kk < BK; kk++) {
            ulonglong2 av0 = *(const ulonglong2*)&As[kk][ty * 8];
            ulonglong2 av1 = *(const ulonglong2*)&As[kk][ty * 8 + 4];
            float4 bq = *(const float4*)&Bs[kk][tx * 4];
            u64 b0 = splat2(bq.x), b1 = splat2(bq.y), b2 = splat2(bq.z), b3 = splat2(bq.w);
            fma2(acc[0][0], av0.x, b0); fma2(acc[0][1], av0.x, b1);
            fma2(acc[0][2], av0.x, b2); fma2(acc[0][3], av0.x, b3);
            fma2(acc[1][0], av0.y, b0); fma2(acc[1][1], av0.y, b1);
            fma2(acc[1][2], av0.y, b2); fma2(acc[1][3], av0.y, b3);
            fma2(acc[2][0], av1.x, b0); fma2(acc[2][1], av1.x, b1);
            fma2(acc[2][2], av1.x, b2); fma2(acc[2][3], av1.x, b3);
            fma2(acc[3][0], av1.y, b0); fma2(acc[3][1], av1.y, b1);
            fma2(acc[3][2], av1.y, b2); fma2(acc[3][3], av1.y, b3);
        }
        __syncthreads();
    }

    float4 biv = *(const float4*)(bias + n0 + tx * 4);
#pragma unroll
    for (int p = 0; p < 4; p++) {
        float2 c0 = unpk(acc[p][0]), c1 = unpk(acc[p][1]);
        float2 c2 = unpk(acc[p][2]), c3 = unpk(acc[p][3]);
        int m = m0 + ty * 8 + p * 2;
        float4 oe = {c0.x + biv.x, c1.x + biv.y, c2.x + biv.z, c3.x + biv.w};
        float4 oo = {c0.y + biv.x, c1.y + biv.y, c2.y + biv.z, c3.y + biv.w};
        *(float4*)(g_GX + (size_t)m * G3 + n0 + tx * 4)       = oe;
        *(float4*)(g_GX + (size_t)(m + 1) * G3 + n0 + tx * 4) = oo;
    }
}

// ---------------- persistent recurrence: 128 CTAs x 512 thr ----------------
// Mapping A (matvec): tid = u(8) x bo(4) x ks(16); thread: unit u, batch octet bo,
//   k-slice [64ks, 64ks+64). R loaded once per (k,u,g) via LDS.32, splatted, reused
//   across 8 batches via f32x2 (h packed along batch: h layout [k][b]).
// Mapping B (gates): threads 0..255: u2 = tid&7, b2 = tid>>3.
// Smem: Rs[k*24 + g*8 + u] (96 KB) + red[(ks*8+u)*100 + g*32 + bo*8 + bl] (51.2 KB).
__global__ void __launch_bounds__(NTHR, 1)
gru_persist(const int* __restrict__ x, const float* __restrict__ RT,
            const float* __restrict__ bias, float* __restrict__ out, int out_size) {
    extern __shared__ float sm[];
    float* Rs  = sm;             // 24576 floats
    float* red = sm + 24576;     // 12800 floats

    const int c   = blockIdx.x;
    const int j0  = c * 8;
    const int tid = threadIdx.x;
    // mapping A
    const int u  = tid & 7;
    const int bo = (tid >> 3) & 3;
    const int ks = tid >> 5;            // warp index = k-slice (0..15)
    // mapping B
    const bool gates = (tid < 256);
    const int u2 = tid & 7;
    const int b2 = tid >> 3;            // valid when gates
    const int j2 = j0 + u2;

    // stage R once: Rs[k*24 + g*8 + u]
    for (int s = tid; s < 1024 * 24; s += NTHR) {
        int k = s / 24, r = s % 24, g = r >> 3, uu = r & 7;
        Rs[k * 24 + g * 8 + uu] = RT[(size_t)k * G3 + g * 1024 + j0 + uu];
    }
    float brz = 0.0f, brr = 0.0f, brn = 0.0f;
    if (gates) {
        brz = bias[G3 + j2];
        brr = bias[G3 + 1024 + j2];
        brn = bias[G3 + 2048 + j2];
    }
    __syncthreads();

    const float* gx_row = gates ? (g_GX + (size_t)b2 * T_ * G3) : g_GX;
    const int*   xrow   = gates ? (x + b2 * T_) : x;
    const int    k0     = ks * 64;
    u64*         redu   = (u64*)red;
    const int    rb     = ((ks * 8 + u) * 100 + bo * 8) >> 1;   // u64 index; +16 per gate
    const int    rdbase = gates ? (b2 & 7) : 0;
    const int    rdbo   = gates ? ((b2 >> 3) * 8) : 0;
    const bool   write_state = (out_size >= B_ * T_ * H_ + B_ * H_);

    for (int t = 0; t < T_; t++) {
        const float* hcur = &g_h2[t & 1][0][0];

        // prefetch gate-phase inputs (latency hidden under matvec)
        float xz = 0.f, xr = 0.f, xn = 0.f, hp = 0.f;
        int tok = 1;
        if (gates) {
            xz  = __ldcs(gx_row + (size_t)t * G3 + j2);
            xr  = __ldcs(gx_row + (size_t)t * G3 + 1024 + j2);
            xn  = __ldcs(gx_row + (size_t)t * G3 + 2048 + j2);
            hp  = __ldcg(hcur + j2 * B_ + b2);
            tok = __ldg(xrow + t);
        }

        // ---- matvec partial over 64-k slice (mapping A) ----
        u64 az0 = 0, az1 = 0, az2 = 0, az3 = 0;
        u64 ar0 = 0, ar1 = 0, ar2 = 0, ar3 = 0;
        u64 an0 = 0, an1 = 0, an2 = 0, an3 = 0;
        const float* hk = hcur + (size_t)k0 * B_ + bo * 8;
        const float* rk = Rs + k0 * 24 + u;
#pragma unroll 4
        for (int k = 0; k < 64; k++) {
            ulonglong2 ha = __ldcg((const ulonglong2*)hk);
            ulonglong2 hb = __ldcg((const ulonglong2*)(hk + 4));
            u64 rz = splat2(rk[0]);
            u64 rr = splat2(rk[8]);
            u64 rn = splat2(rk[16]);
            fma2(az0, ha.x, rz); fma2(az1, ha.y, rz); fma2(az2, hb.x, rz); fma2(az3, hb.y, rz);
            fma2(ar0, ha.x, rr); fma2(ar1, ha.y, rr); fma2(ar2, hb.x, rr); fma2(ar3, hb.y, rr);
            fma2(an0, ha.x, rn); fma2(an1, ha.y, rn); fma2(an2, hb.x, rn); fma2(an3, hb.y, rn);
            hk += B_; rk += 24;
        }
        redu[rb + 0]  = az0; redu[rb + 1]  = az1; redu[rb + 2]  = az2; redu[rb + 3]  = az3;
        redu[rb + 16] = ar0; redu[rb + 17] = ar1; redu[rb + 18] = ar2; redu[rb + 19] = ar3;
        redu[rb + 32] = an0; redu[rb + 33] = an1; redu[rb + 34] = an2; redu[rb + 35] = an3;
        __syncthreads();

        // ---- reduce + gates (threads 0..255) ----
        if (gates) {
            float az = 0.0f, ar = 0.0f, an = 0.0f;
#pragma unroll
            for (int kss = 0; kss < 16; kss++) {
                int o = (kss * 8 + u2) * 100 + rdbo + rdbase;
                az += red[o];
                ar += red[o + 32];
                an += red[o + 64];
            }
            float zz = 1.0f / (1.0f + expf(-(xz + az + brz)));
            float rg = 1.0f / (1.0f + expf(-(xr + ar + brr)));
            float hh = tanhf(xn + rg * (an + brn));
            float hnew = zz * hp + (1.0f - zz) * hh;
            if (tok == 0) hnew = hp;

            out[((size_t)b2 * T_ + t) * H_ + j2] = hnew;
            g_h2[(t + 1) & 1][j2][b2] = hnew;
            if (t == T_ - 1 && write_state)
                out[(size_t)B_ * T_ * H_ + (size_t)b2 * H_ + j2] = hnew;
        }

        // ---- grid barrier: release arrive + acquire spin (no L1 flush) ----
        if (t < T_ - 1) {
            __syncthreads();   // all h writes of this CTA done
            if (tid == 0) {
                unsigned int* ctr = &g_counters[t + 1];
                asm volatile("red.release.gpu.global.add.u32 [%0], %1;"
                             :: "l"(ctr), "r"(1u) : "memory");
                unsigned int v;
                do {
                    asm volatile("ld.acquire.gpu.global.u32 %0, [%1];"
                                 : "=r"(v) : "l"(ctr) : "memory");
                } while (v < (unsigned)NCTA);
            }
            __syncthreads();
        }
    }
}

// ---------------- launch ----------------
extern "C" void kernel_launch(void* const* d_in, const int* in_sizes, int n_in,
                              void* d_out, int out_size) {
    const int*   x      = (const int*)d_in[0];
    const float* hidden = (const float*)d_in[1];
    const float* emb    = (const float*)d_in[2];
    const float* W      = (const float*)d_in[3];
    const float* RT     = (const float*)d_in[4];
    const float* bias   = (const float*)d_in[5];
    float*       out    = (float*)d_out;

    const int smem = (24576 + 12800) * 4;   // 149504 B
    cudaFuncSetAttribute(gru_persist, cudaFuncAttributeMaxDynamicSharedMemorySize, smem);

    // gx first, then init, then gru (ncu -s 5 -c 1 then lands on gru_persist)
    dim3 grid_gx(16384 / BM, G3 / BN);
    gx_kernel<<<grid_gx, 256>>>(x, emb, W, bias);

    init_kernel<<<64, 256>>>(hidden);

    gru_persist<<<NCTA, NTHR, smem>>>(x, RT, bias, out, out_size);
}